// round 1
// baseline (speedup 1.0000x reference)
#include <cuda_runtime.h>
#include <math.h>

#define BATCH 4
#define CDIM 384
#define NHEADS 8
#define CPH 48
#define NPIX 16384
#define C3 1152

// ---------------- scratch (static device globals; no allocation) ----------------
__device__ float g_qkv1[(size_t)BATCH * C3 * NPIX];     // 1x1 conv out   (302 MB)
__device__ float g_qkv2[(size_t)BATCH * C3 * NPIX];     // depthwise out  (302 MB)
__device__ float g_norm[BATCH * 768];                    // 1/||row|| for q,k
__device__ float g_part[32 * 16 * 2304];                 // partial q.k^T
__device__ float g_logits[32 * 2304];
__device__ float g_probs[32 * 2304];
__device__ float g_attnout[(size_t)BATCH * CDIM * NPIX]; // attn @ v       (100 MB)
__device__ float g_pos1[(size_t)BATCH * CDIM * NPIX];    // gelu(dw(v))    (100 MB)

// ---------------- SGEMM: C[b] = A(MxK) * B[b](KxN), all row-major ----------------
// BM=BN=128, BK=8, 256 threads, 8x8 per thread.
__global__ void sgemm128(const float* __restrict__ A, const float* __restrict__ Bm,
                         float* __restrict__ Cm, int N, int K,
                         size_t strideB, size_t strideC) {
    __shared__ float As[8][128];
    __shared__ float Bs[8][128];
    const float* Bp = Bm + (size_t)blockIdx.z * strideB;
    float* Cp = Cm + (size_t)blockIdx.z * strideC;
    const int tid = threadIdx.x;
    const int brow = blockIdx.y * 128;
    const int bcol = blockIdx.x * 128;
    const int aRow = tid >> 1;
    const int aCol = (tid & 1) * 4;
    const int bRow = tid >> 5;
    const int bCol = (tid & 31) * 4;
    const int tx = tid & 15, ty = tid >> 4;

    float acc[8][8];
#pragma unroll
    for (int i = 0; i < 8; i++)
#pragma unroll
        for (int j = 0; j < 8; j++) acc[i][j] = 0.f;

    for (int k0 = 0; k0 < K; k0 += 8) {
        float4 a4 = *(const float4*)(A + (size_t)(brow + aRow) * K + k0 + aCol);
        As[aCol + 0][aRow] = a4.x;
        As[aCol + 1][aRow] = a4.y;
        As[aCol + 2][aRow] = a4.z;
        As[aCol + 3][aRow] = a4.w;
        float4 b4 = *(const float4*)(Bp + (size_t)(k0 + bRow) * N + bcol + bCol);
        *(float4*)&Bs[bRow][bCol] = b4;
        __syncthreads();
#pragma unroll
        for (int kk = 0; kk < 8; kk++) {
            float4 ra0 = *(const float4*)&As[kk][ty * 8];
            float4 ra1 = *(const float4*)&As[kk][ty * 8 + 4];
            float4 rb0 = *(const float4*)&Bs[kk][tx * 8];
            float4 rb1 = *(const float4*)&Bs[kk][tx * 8 + 4];
            float ra[8] = {ra0.x, ra0.y, ra0.z, ra0.w, ra1.x, ra1.y, ra1.z, ra1.w};
            float rb[8] = {rb0.x, rb0.y, rb0.z, rb0.w, rb1.x, rb1.y, rb1.z, rb1.w};
#pragma unroll
            for (int i = 0; i < 8; i++)
#pragma unroll
                for (int j = 0; j < 8; j++) acc[i][j] += ra[i] * rb[j];
        }
        __syncthreads();
    }
#pragma unroll
    for (int i = 0; i < 8; i++) {
        size_t r = (size_t)(brow + ty * 8 + i) * N + bcol + tx * 8;
#pragma unroll
        for (int j = 0; j < 8; j += 4) {
            float4 v = make_float4(acc[i][j], acc[i][j + 1], acc[i][j + 2], acc[i][j + 3]);
            *(float4*)(Cp + r + j) = v;
        }
    }
}

// ---------------- depthwise 3x3, SAME padding ----------------
// MODE 0: plain write; MODE 1: gelu(exact) write; MODE 2: add into out
template <int MODE>
__global__ void dwconv3x3(const float* __restrict__ in, const float* __restrict__ w,
                          float* __restrict__ out, int CH,
                          size_t inStride, size_t outStride, int total) {
    int idx = blockIdx.x * 256 + threadIdx.x;
    if (idx >= total) return;
    int x = idx & 127;
    int y = (idx >> 7) & 127;
    int ch = (idx >> 14) % CH;
    int b = idx / (CH << 14);
    const float* ip = in + (size_t)b * inStride + (size_t)ch * NPIX;
    const float* wp = w + ch * 9;
    float s = 0.f;
#pragma unroll
    for (int ky = 0; ky < 3; ky++) {
        int yy = y + ky - 1;
        if (yy < 0 || yy > 127) continue;
#pragma unroll
        for (int kx = 0; kx < 3; kx++) {
            int xx = x + kx - 1;
            if (xx < 0 || xx > 127) continue;
            s += wp[ky * 3 + kx] * ip[yy * 128 + xx];
        }
    }
    float* op = out + (size_t)b * outStride + (size_t)ch * NPIX + y * 128 + x;
    if (MODE == 0) {
        *op = s;
    } else if (MODE == 1) {
        *op = 0.5f * s * (1.0f + erff(s * 0.70710678118654752f));
    } else {
        *op += s;
    }
}

// ---------------- per-row inverse L2 norms for q,k ----------------
__global__ void rownorm_kernel(const float* __restrict__ qk, float* __restrict__ invn) {
    int row = blockIdx.x;  // 0 .. BATCH*768-1
    int b = row / 768, c = row % 768;
    const float* p = qk + ((size_t)b * C3 + c) * NPIX;
    float s = 0.f;
    for (int i = threadIdx.x; i < NPIX; i += 256) {
        float v = p[i];
        s += v * v;
    }
    __shared__ float red[8];
#pragma unroll
    for (int o = 16; o; o >>= 1) s += __shfl_down_sync(~0u, s, o);
    if ((threadIdx.x & 31) == 0) red[threadIdx.x >> 5] = s;
    __syncthreads();
    if (threadIdx.x < 8) {
        s = red[threadIdx.x];
#pragma unroll
        for (int o = 4; o; o >>= 1) s += __shfl_down_sync(0xffu, s, o);
        if (threadIdx.x == 0) invn[row] = 1.0f / fmaxf(sqrtf(s), 1e-12f);
    }
}

// ---------------- partial q.k^T over an n-split of 1024 ----------------
__global__ void attn_partial(const float* __restrict__ qkv, float* __restrict__ part) {
    __shared__ float qs[48][65];
    __shared__ float ks[48][65];
    const int split = blockIdx.x, h = blockIdx.y, b = blockIdx.z;
    const int tid = threadIdx.x;
    const float* qbase = qkv + ((size_t)b * C3 + h * CPH) * NPIX;
    const float* kbase = qkv + ((size_t)b * C3 + 384 + h * CPH) * NPIX;
    const int tx = tid & 15, ty = tid >> 4;
    const int c0 = ty * 3, d0 = tx * 3;
    float acc[3][3];
#pragma unroll
    for (int i = 0; i < 3; i++)
#pragma unroll
        for (int j = 0; j < 3; j++) acc[i][j] = 0.f;

    for (int chunk = 0; chunk < 16; chunk++) {
        int n0 = split * 1024 + chunk * 64;
        __syncthreads();
#pragma unroll
        for (int r = 0; r < 3; r++) {
            int v = tid + r * 256;  // 0..767
            int row = v >> 4;
            int col = (v & 15) << 2;
            float4 q4 = *(const float4*)(qbase + (size_t)row * NPIX + n0 + col);
            qs[row][col] = q4.x; qs[row][col + 1] = q4.y;
            qs[row][col + 2] = q4.z; qs[row][col + 3] = q4.w;
            float4 k4 = *(const float4*)(kbase + (size_t)row * NPIX + n0 + col);
            ks[row][col] = k4.x; ks[row][col + 1] = k4.y;
            ks[row][col + 2] = k4.z; ks[row][col + 3] = k4.w;
        }
        __syncthreads();
#pragma unroll 16
        for (int i = 0; i < 64; i++) {
            float q0 = qs[c0][i], q1 = qs[c0 + 1][i], q2 = qs[c0 + 2][i];
            float k0v = ks[d0][i], k1v = ks[d0 + 1][i], k2v = ks[d0 + 2][i];
            acc[0][0] += q0 * k0v; acc[0][1] += q0 * k1v; acc[0][2] += q0 * k2v;
            acc[1][0] += q1 * k0v; acc[1][1] += q1 * k1v; acc[1][2] += q1 * k2v;
            acc[2][0] += q2 * k0v; acc[2][1] += q2 * k1v; acc[2][2] += q2 * k2v;
        }
    }
    float* pp = part + ((size_t)((b * NHEADS + h) * 16 + split)) * 2304;
#pragma unroll
    for (int i = 0; i < 3; i++)
#pragma unroll
        for (int j = 0; j < 3; j++) pp[(c0 + i) * 48 + d0 + j] = acc[i][j];
}

// ---------------- sum splits, apply norms & temperature ----------------
__global__ void attn_reduce(const float* __restrict__ part, const float* __restrict__ invn,
                            const float* __restrict__ temp, float* __restrict__ logits) {
    int idx = blockIdx.x * 256 + threadIdx.x;  // over 32*2304
    if (idx >= 32 * 2304) return;
    int bh = idx / 2304, o = idx % 2304;
    int b = bh / NHEADS, h = bh % NHEADS;
    int c = o / 48, d = o % 48;
    float s = 0.f;
#pragma unroll
    for (int sp = 0; sp < 16; sp++) s += part[((size_t)bh * 16 + sp) * 2304 + o];
    float inq = invn[b * 768 + h * CPH + c];
    float ink = invn[b * 768 + 384 + h * CPH + d];
    logits[idx] = s * inq * ink * temp[h];
}

// ---------------- dual softmax + blend ----------------
__global__ void softmax_blend(const float* __restrict__ logits, const int* __restrict__ mask,
                              const float* __restrict__ wb, float* __restrict__ probs) {
    int row = blockIdx.x;  // (b*8+h)*48 + c, 0..1535
    int c = row % 48;
    int h = (row / 48) % NHEADS;
    int lane = threadIdx.x;  // 32 threads
    int d1 = lane + 32;
    const float* lp = logits + (size_t)row * 48;
    const int* mp = mask + (h * 48 + c) * 48;
    bool v1ok = d1 < 48;
    float a0 = lp[lane];
    float a1 = v1ok ? lp[d1] : -INFINITY;
    float b0 = (mp[lane] == 0) ? -1e9f : a0;
    float b1 = v1ok ? ((mp[d1] == 0) ? -1e9f : a1) : -INFINITY;
    float mA = fmaxf(a0, a1), mB = fmaxf(b0, b1);
#pragma unroll
    for (int o = 16; o; o >>= 1) {
        mA = fmaxf(mA, __shfl_xor_sync(~0u, mA, o));
        mB = fmaxf(mB, __shfl_xor_sync(~0u, mB, o));
    }
    float eA0 = expf(a0 - mA);
    float eA1 = v1ok ? expf(a1 - mA) : 0.f;
    float eB0 = expf(b0 - mB);
    float eB1 = v1ok ? expf(b1 - mB) : 0.f;
    float sA = eA0 + eA1, sB = eB0 + eB1;
#pragma unroll
    for (int o = 16; o; o >>= 1) {
        sA += __shfl_xor_sync(~0u, sA, o);
        sB += __shfl_xor_sync(~0u, sB, o);
    }
    float w0 = wb[0], w1 = wb[1];
    float wm = fmaxf(w0, w1);
    float ew0 = expf(w0 - wm), ew1 = expf(w1 - wm);
    float wsum = ew0 + ew1;
    float blend0 = ew0 / wsum, blend1 = ew1 / wsum;
    float* pp = probs + (size_t)row * 48;
    pp[lane] = blend0 * eA0 / sA + blend1 * eB0 / sB;
    if (v1ok) pp[d1] = blend0 * eA1 / sA + blend1 * eB1 / sB;
}

// ---------------- out = attn @ v ----------------
__global__ void attnv(const float* __restrict__ probs, const float* __restrict__ qkv2,
                      float* __restrict__ out) {
    __shared__ float a_s[2304];
    const int h = blockIdx.y, b = blockIdx.z;
    const int n = blockIdx.x * 128 + threadIdx.x;
    const float* ap = probs + (size_t)(b * NHEADS + h) * 2304;
    for (int i = threadIdx.x; i < 2304; i += 128) a_s[i] = ap[i];
    __syncthreads();
    const float* vbase = qkv2 + ((size_t)b * C3 + 768 + h * CPH) * NPIX + n;
    float vr[48];
#pragma unroll
    for (int d = 0; d < 48; d++) vr[d] = vbase[(size_t)d * NPIX];
    float* obase = out + ((size_t)b * CDIM + h * CPH) * NPIX + n;
#pragma unroll 4
    for (int c = 0; c < 48; c++) {
        float acc = 0.f;
#pragma unroll
        for (int d = 0; d < 48; d++) acc += a_s[c * 48 + d] * vr[d];
        obase[(size_t)c * NPIX] = acc;
    }
}

// ---------------- launch ----------------
extern "C" void kernel_launch(void* const* d_in, const int* in_sizes, int n_in,
                              void* d_out, int out_size) {
    const float* x           = (const float*)d_in[0];
    const int*   mask        = (const int*)d_in[1];
    const float* qkv_w       = (const float*)d_in[2];
    const float* dw_w        = (const float*)d_in[3];
    const float* proj_w      = (const float*)d_in[4];
    const float* temperature = (const float*)d_in[5];
    const float* w_blend     = (const float*)d_in[6];
    const float* pos_w1      = (const float*)d_in[7];
    const float* pos_w2      = (const float*)d_in[8];
    float* out = (float*)d_out;

    float *qkv1, *qkv2, *norm, *part, *logits, *probs, *attnout, *pos1;
    cudaGetSymbolAddress((void**)&qkv1, g_qkv1);
    cudaGetSymbolAddress((void**)&qkv2, g_qkv2);
    cudaGetSymbolAddress((void**)&norm, g_norm);
    cudaGetSymbolAddress((void**)&part, g_part);
    cudaGetSymbolAddress((void**)&logits, g_logits);
    cudaGetSymbolAddress((void**)&probs, g_probs);
    cudaGetSymbolAddress((void**)&attnout, g_attnout);
    cudaGetSymbolAddress((void**)&pos1, g_pos1);

    // 1) qkv 1x1 conv: (1152x384) @ (384x16384) per batch
    sgemm128<<<dim3(NPIX / 128, C3 / 128, BATCH), 256>>>(
        qkv_w, x, qkv1, NPIX, CDIM, (size_t)CDIM * NPIX, (size_t)C3 * NPIX);

    // 2) depthwise 3x3 over 1152 channels
    {
        int total = BATCH * C3 * NPIX;
        dwconv3x3<0><<<(total + 255) / 256, 256>>>(
            qkv1, dw_w, qkv2, C3, (size_t)C3 * NPIX, (size_t)C3 * NPIX, total);
    }

    // 3) q,k row norms
    rownorm_kernel<<<BATCH * 768, 256>>>(qkv2, norm);

    // 4) q.k^T partials + reduce
    attn_partial<<<dim3(16, NHEADS, BATCH), 256>>>(qkv2, part);
    attn_reduce<<<(32 * 2304 + 255) / 256, 256>>>(part, norm, temperature, logits);

    // 5) dual softmax blend
    softmax_blend<<<BATCH * NHEADS * 48, 32>>>(logits, mask, w_blend, probs);

    // 6) attn @ v
    attnv<<<dim3(NPIX / 128, NHEADS, BATCH), 128>>>(probs, qkv2, attnout);

    // 7) proj 1x1 conv into d_out
    sgemm128<<<dim3(NPIX / 128, CDIM / 128, BATCH), 256>>>(
        proj_w, attnout, out, NPIX, CDIM, (size_t)CDIM * NPIX, (size_t)CDIM * NPIX);

    // 8) pos path: dw3x3 -> gelu -> dw3x3, added into d_out
    {
        int total = BATCH * CDIM * NPIX;
        dwconv3x3<1><<<(total + 255) / 256, 256>>>(
            qkv2 + (size_t)768 * NPIX, pos_w1, pos1, CDIM,
            (size_t)C3 * NPIX, (size_t)CDIM * NPIX, total);
        dwconv3x3<2><<<(total + 255) / 256, 256>>>(
            pos1, pos_w2, out, CDIM,
            (size_t)CDIM * NPIX, (size_t)CDIM * NPIX, total);
    }
}

// round 3
// speedup vs baseline: 1.2333x; 1.2333x over previous
#include <cuda_runtime.h>
#include <cuda_bf16.h>
#include <math.h>
#include <cstdint>

#define BATCH 4
#define CDIM 384
#define NHEADS 8
#define CPH 48
#define NPIX 16384
#define C3 1152

// ================= scratch (static device globals; no allocation) =================
__device__ float g_qkv1[(size_t)BATCH * C3 * NPIX];     // 1x1 conv out
__device__ float g_qkv2[(size_t)BATCH * C3 * NPIX];     // depthwise out
__device__ float g_norm[BATCH * 768];
__device__ float g_part[32 * 16 * 2304];
__device__ float g_logits[32 * 2304];
__device__ float g_probs[32 * 2304];
__device__ float g_pos1[(size_t)BATCH * CDIM * NPIX];
// bf16 split operands
__device__ __nv_bfloat16 g_xT_hi[(size_t)BATCH * NPIX * CDIM];
__device__ __nv_bfloat16 g_xT_lo[(size_t)BATCH * NPIX * CDIM];
__device__ __nv_bfloat16 g_aT_hi[(size_t)BATCH * NPIX * CDIM];
__device__ __nv_bfloat16 g_aT_lo[(size_t)BATCH * NPIX * CDIM];
__device__ __nv_bfloat16 g_wq_hi[C3 * CDIM];
__device__ __nv_bfloat16 g_wq_lo[C3 * CDIM];
__device__ __nv_bfloat16 g_wp_hi[CDIM * CDIM];
__device__ __nv_bfloat16 g_wp_lo[CDIM * CDIM];

// ================= helpers =================
__device__ __forceinline__ uint32_t smem_u32(const void* p) {
    uint32_t a;
    asm("{ .reg .u64 t; cvta.to.shared.u64 t, %1; cvt.u32.u64 %0, t; }" : "=r"(a) : "l"(p));
    return a;
}
__device__ __forceinline__ void cp16(uint32_t s, const void* g) {
    asm volatile("cp.async.cg.shared.global [%0], [%1], 16;" :: "r"(s), "l"(g));
}
__device__ __forceinline__ void mma16816(float* c, const uint32_t* a, uint32_t b0, uint32_t b1) {
    asm volatile(
        "mma.sync.aligned.m16n8k16.row.col.f32.bf16.bf16.f32 "
        "{%0,%1,%2,%3}, {%4,%5,%6,%7}, {%8,%9}, {%0,%1,%2,%3};"
        : "+f"(c[0]), "+f"(c[1]), "+f"(c[2]), "+f"(c[3])
        : "r"(a[0]), "r"(a[1]), "r"(a[2]), "r"(a[3]), "r"(b0), "r"(b1));
}

// ================= 3xBF16 HMMA GEMM =================
// C[b] (M x 16384, row-major) = A (M x 384) * B[b]^T,  B operand stored [16384][384].
// CTA tile 128x128, 8 warps (warp tile 32x64), K chunks of 32, cp.async double buffer.
// SMEM per buffer: 4 tiles of 128 rows x (32+8) bf16 = 10240B each; buffer stride 40960.
#define TILE_B 10240
#define BUF_B 40960
#define GEMM_SMEM (2 * BUF_B)

__global__ void __launch_bounds__(256) gemm_hmma(
    const __nv_bfloat16* __restrict__ Ah, const __nv_bfloat16* __restrict__ Al,
    const __nv_bfloat16* __restrict__ Bh, const __nv_bfloat16* __restrict__ Bl,
    float* __restrict__ C, size_t strideB, size_t strideC) {
    extern __shared__ char sm[];
    const uint32_t sb = smem_u32(sm);
    const int tid = threadIdx.x;
    const int m0 = blockIdx.x * 128;
    const int n0 = blockIdx.y * 128;
    const __nv_bfloat16* bhp = Bh + blockIdx.z * strideB;
    const __nv_bfloat16* blp = Bl + blockIdx.z * strideB;
    float* Cp = C + blockIdx.z * strideC;

    const int wid = tid >> 5, lane = tid & 31;
    const int wm = (wid & 3) * 32, wn = (wid >> 2) * 64;
    const int qr = lane >> 2, qc = lane & 3;

    float acc[2][8][4];
#pragma unroll
    for (int i = 0; i < 2; i++)
#pragma unroll
        for (int j = 0; j < 8; j++)
#pragma unroll
            for (int t = 0; t < 4; t++) acc[i][j][t] = 0.f;

    // per-thread load coordinates (2 uint4 per tile per thread)
    const int row0 = tid >> 2, c40 = tid & 3;
    const int row1 = (tid + 256) >> 2, c41 = tid & 3;  // (tid+256)&3 == tid&3

    auto issue = [&](int ch, int b) {
        const int k0 = ch * 32;
        const uint32_t bb = sb + b * BUF_B;
        {
            uint32_t so = row0 * 80 + c40 * 16;
            const char* ga = (const char*)(Ah + (size_t)(m0 + row0) * 384 + k0) + c40 * 16;
            const char* gl = (const char*)(Al + (size_t)(m0 + row0) * 384 + k0) + c40 * 16;
            const char* gb = (const char*)(bhp + (size_t)(n0 + row0) * 384 + k0) + c40 * 16;
            const char* gc = (const char*)(blp + (size_t)(n0 + row0) * 384 + k0) + c40 * 16;
            cp16(bb + so, ga);
            cp16(bb + TILE_B + so, gl);
            cp16(bb + 2 * TILE_B + so, gb);
            cp16(bb + 3 * TILE_B + so, gc);
        }
        {
            uint32_t so = row1 * 80 + c41 * 16;
            const char* ga = (const char*)(Ah + (size_t)(m0 + row1) * 384 + k0) + c41 * 16;
            const char* gl = (const char*)(Al + (size_t)(m0 + row1) * 384 + k0) + c41 * 16;
            const char* gb = (const char*)(bhp + (size_t)(n0 + row1) * 384 + k0) + c41 * 16;
            const char* gc = (const char*)(blp + (size_t)(n0 + row1) * 384 + k0) + c41 * 16;
            cp16(bb + so, ga);
            cp16(bb + TILE_B + so, gl);
            cp16(bb + 2 * TILE_B + so, gb);
            cp16(bb + 3 * TILE_B + so, gc);
        }
        asm volatile("cp.async.commit_group;");
    };

    issue(0, 0);

#pragma unroll 1
    for (int ch = 0; ch < 12; ch++) {
        if (ch < 11) {
            issue(ch + 1, (ch + 1) & 1);
            asm volatile("cp.async.wait_group 1;");
        } else {
            asm volatile("cp.async.wait_group 0;");
        }
        __syncthreads();

        const char* buf = sm + (ch & 1) * BUF_B;
#pragma unroll
        for (int kc = 0; kc < 32; kc += 16) {
            // A fragments (hi, lo) for both m-blocks
            uint32_t aH[2][4], aL[2][4];
#pragma unroll
            for (int i = 0; i < 2; i++) {
                uint32_t o = (uint32_t)(wm + i * 16 + qr) * 80 + (uint32_t)(kc + qc * 2) * 2;
                aH[i][0] = *(const uint32_t*)(buf + o);
                aH[i][1] = *(const uint32_t*)(buf + o + 640);
                aH[i][2] = *(const uint32_t*)(buf + o + 16);
                aH[i][3] = *(const uint32_t*)(buf + o + 656);
                aL[i][0] = *(const uint32_t*)(buf + TILE_B + o);
                aL[i][1] = *(const uint32_t*)(buf + TILE_B + o + 640);
                aL[i][2] = *(const uint32_t*)(buf + TILE_B + o + 16);
                aL[i][3] = *(const uint32_t*)(buf + TILE_B + o + 656);
            }
#pragma unroll
            for (int j = 0; j < 8; j++) {
                uint32_t ob = (uint32_t)(wn + j * 8 + qr) * 80 + (uint32_t)(kc + qc * 2) * 2;
                uint32_t bh0 = *(const uint32_t*)(buf + 2 * TILE_B + ob);
                uint32_t bh1 = *(const uint32_t*)(buf + 2 * TILE_B + ob + 16);
                uint32_t bl0 = *(const uint32_t*)(buf + 3 * TILE_B + ob);
                uint32_t bl1 = *(const uint32_t*)(buf + 3 * TILE_B + ob + 16);
#pragma unroll
                for (int i = 0; i < 2; i++) {
                    mma16816(acc[i][j], aH[i], bh0, bh1);
                    mma16816(acc[i][j], aH[i], bl0, bl1);
                    mma16816(acc[i][j], aL[i], bh0, bh1);
                }
            }
        }
        __syncthreads();
    }

    // epilogue
#pragma unroll
    for (int i = 0; i < 2; i++) {
        int r0 = m0 + wm + i * 16 + qr;
#pragma unroll
        for (int j = 0; j < 8; j++) {
            int cc = n0 + wn + j * 8 + qc * 2;
            float* cp = Cp + (size_t)r0 * NPIX + cc;
            *(float2*)cp = make_float2(acc[i][j][0], acc[i][j][1]);
            *(float2*)(cp + (size_t)8 * NPIX) = make_float2(acc[i][j][2], acc[i][j][3]);
        }
    }
}

// ================= fp32 -> bf16 hi/lo converters =================
__global__ void cvt_split(const float* __restrict__ in, __nv_bfloat16* __restrict__ hi,
                          __nv_bfloat16* __restrict__ lo, int n) {
    int i = blockIdx.x * 256 + threadIdx.x;
    if (i >= n) return;
    float v = in[i];
    __nv_bfloat16 h = __float2bfloat16_rn(v);
    hi[i] = h;
    lo[i] = __float2bfloat16_rn(v - __bfloat162float(h));
}

__global__ void transpose_split(const float* __restrict__ x, __nv_bfloat16* __restrict__ th,
                                __nv_bfloat16* __restrict__ tl) {
    __shared__ float t[32][33];
    int b = blockIdx.z;
    int n0 = blockIdx.x * 32, c0 = blockIdx.y * 32;
    t[threadIdx.y][threadIdx.x] =
        x[((size_t)b * CDIM + c0 + threadIdx.y) * NPIX + n0 + threadIdx.x];
    __syncthreads();
    float v = t[threadIdx.x][threadIdx.y];
    __nv_bfloat16 h = __float2bfloat16_rn(v);
    size_t o = ((size_t)b * NPIX + n0 + threadIdx.y) * CDIM + c0 + threadIdx.x;
    th[o] = h;
    tl[o] = __float2bfloat16_rn(v - __bfloat162float(h));
}

// ================= depthwise 3x3, SAME =================
template <int MODE>
__global__ void dwconv3x3(const float* __restrict__ in, const float* __restrict__ w,
                          float* __restrict__ out, int CH,
                          size_t inStride, size_t outStride, int total) {
    int idx = blockIdx.x * 256 + threadIdx.x;
    if (idx >= total) return;
    int x = idx & 127;
    int y = (idx >> 7) & 127;
    int ch = (idx >> 14) % CH;
    int b = idx / (CH << 14);
    const float* ip = in + (size_t)b * inStride + (size_t)ch * NPIX;
    const float* wp = w + ch * 9;
    float s = 0.f;
    if (x > 0 && x < 127 && y > 0 && y < 127) {
        const float* p = ip + (y - 1) * 128 + x - 1;
#pragma unroll
        for (int ky = 0; ky < 3; ky++) {
            s += wp[ky * 3 + 0] * p[ky * 128 + 0];
            s += wp[ky * 3 + 1] * p[ky * 128 + 1];
            s += wp[ky * 3 + 2] * p[ky * 128 + 2];
        }
    } else {
#pragma unroll
        for (int ky = 0; ky < 3; ky++) {
            int yy = y + ky - 1;
            if (yy < 0 || yy > 127) continue;
#pragma unroll
            for (int kx = 0; kx < 3; kx++) {
                int xx = x + kx - 1;
                if (xx < 0 || xx > 127) continue;
                s += wp[ky * 3 + kx] * ip[yy * 128 + xx];
            }
        }
    }
    float* op = out + (size_t)b * outStride + (size_t)ch * NPIX + y * 128 + x;
    if (MODE == 0) *op = s;
    else if (MODE == 1) *op = 0.5f * s * (1.0f + erff(s * 0.70710678118654752f));
    else *op += s;
}

// ================= per-row inverse L2 norms =================
__global__ void rownorm_kernel(const float* __restrict__ qk, float* __restrict__ invn) {
    int row = blockIdx.x;
    int b = row / 768, c = row % 768;
    const float* p = qk + ((size_t)b * C3 + c) * NPIX;
    float s = 0.f;
    for (int i = threadIdx.x; i < NPIX; i += 256) {
        float v = p[i];
        s += v * v;
    }
    __shared__ float red[8];
#pragma unroll
    for (int o = 16; o; o >>= 1) s += __shfl_down_sync(~0u, s, o);
    if ((threadIdx.x & 31) == 0) red[threadIdx.x >> 5] = s;
    __syncthreads();
    if (threadIdx.x < 8) {
        s = red[threadIdx.x];
#pragma unroll
        for (int o = 4; o; o >>= 1) s += __shfl_down_sync(0xffu, s, o);
        if (threadIdx.x == 0) invn[row] = 1.0f / fmaxf(sqrtf(s), 1e-12f);
    }
}

// ================= q.k^T partials =================
__global__ void attn_partial(const float* __restrict__ qkv, float* __restrict__ part) {
    __shared__ float qs[48][65];
    __shared__ float ks[48][65];
    const int split = blockIdx.x, h = blockIdx.y, b = blockIdx.z;
    const int tid = threadIdx.x;
    const float* qbase = qkv + ((size_t)b * C3 + h * CPH) * NPIX;
    const float* kbase = qkv + ((size_t)b * C3 + 384 + h * CPH) * NPIX;
    const int tx = tid & 15, ty = tid >> 4;
    const int c0 = ty * 3, d0 = tx * 3;
    float acc[3][3];
#pragma unroll
    for (int i = 0; i < 3; i++)
#pragma unroll
        for (int j = 0; j < 3; j++) acc[i][j] = 0.f;

    for (int chunk = 0; chunk < 16; chunk++) {
        int n0 = split * 1024 + chunk * 64;
        __syncthreads();
#pragma unroll
        for (int r = 0; r < 3; r++) {
            int v = tid + r * 256;
            int row = v >> 4;
            int col = (v & 15) << 2;
            float4 q4 = *(const float4*)(qbase + (size_t)row * NPIX + n0 + col);
            qs[row][col] = q4.x; qs[row][col + 1] = q4.y;
            qs[row][col + 2] = q4.z; qs[row][col + 3] = q4.w;
            float4 k4 = *(const float4*)(kbase + (size_t)row * NPIX + n0 + col);
            ks[row][col] = k4.x; ks[row][col + 1] = k4.y;
            ks[row][col + 2] = k4.z; ks[row][col + 3] = k4.w;
        }
        __syncthreads();
#pragma unroll 16
        for (int i = 0; i < 64; i++) {
            float q0 = qs[c0][i], q1 = qs[c0 + 1][i], q2 = qs[c0 + 2][i];
            float k0v = ks[d0][i], k1v = ks[d0 + 1][i], k2v = ks[d0 + 2][i];
            acc[0][0] += q0 * k0v; acc[0][1] += q0 * k1v; acc[0][2] += q0 * k2v;
            acc[1][0] += q1 * k0v; acc[1][1] += q1 * k1v; acc[1][2] += q1 * k2v;
            acc[2][0] += q2 * k0v; acc[2][1] += q2 * k1v; acc[2][2] += q2 * k2v;
        }
    }
    float* pp = part + ((size_t)((b * NHEADS + h) * 16 + split)) * 2304;
#pragma unroll
    for (int i = 0; i < 3; i++)
#pragma unroll
        for (int j = 0; j < 3; j++) pp[(c0 + i) * 48 + d0 + j] = acc[i][j];
}

__global__ void attn_reduce(const float* __restrict__ part, const float* __restrict__ invn,
                            const float* __restrict__ temp, float* __restrict__ logits) {
    int idx = blockIdx.x * 256 + threadIdx.x;
    if (idx >= 32 * 2304) return;
    int bh = idx / 2304, o = idx % 2304;
    int b = bh / NHEADS, h = bh % NHEADS;
    int c = o / 48, d = o % 48;
    float s = 0.f;
#pragma unroll
    for (int sp = 0; sp < 16; sp++) s += part[((size_t)bh * 16 + sp) * 2304 + o];
    float inq = invn[b * 768 + h * CPH + c];
    float ink = invn[b * 768 + 384 + h * CPH + d];
    logits[idx] = s * inq * ink * temp[h];
}

__global__ void softmax_blend(const float* __restrict__ logits, const int* __restrict__ mask,
                              const float* __restrict__ wb, float* __restrict__ probs) {
    int row = blockIdx.x;
    int c = row % 48;
    int h = (row / 48) % NHEADS;
    int lane = threadIdx.x;
    int d1 = lane + 32;
    const float* lp = logits + (size_t)row * 48;
    const int* mp = mask + (h * 48 + c) * 48;
    bool v1ok = d1 < 48;
    float a0 = lp[lane];
    float a1 = v1ok ? lp[d1] : -INFINITY;
    float b0 = (mp[lane] == 0) ? -1e9f : a0;
    float b1 = v1ok ? ((mp[d1] == 0) ? -1e9f : a1) : -INFINITY;
    float mA = fmaxf(a0, a1), mB = fmaxf(b0, b1);
#pragma unroll
    for (int o = 16; o; o >>= 1) {
        mA = fmaxf(mA, __shfl_xor_sync(~0u, mA, o));
        mB = fmaxf(mB, __shfl_xor_sync(~0u, mB, o));
    }
    float eA0 = expf(a0 - mA);
    float eA1 = v1ok ? expf(a1 - mA) : 0.f;
    float eB0 = expf(b0 - mB);
    float eB1 = v1ok ? expf(b1 - mB) : 0.f;
    float sA = eA0 + eA1, sB = eB0 + eB1;
#pragma unroll
    for (int o = 16; o; o >>= 1) {
        sA += __shfl_xor_sync(~0u, sA, o);
        sB += __shfl_xor_sync(~0u, sB, o);
    }
    float w0 = wb[0], w1 = wb[1];
    float wm = fmaxf(w0, w1);
    float ew0 = expf(w0 - wm), ew1 = expf(w1 - wm);
    float wsum = ew0 + ew1;
    float blend0 = ew0 / wsum, blend1 = ew1 / wsum;
    float* pp = probs + (size_t)row * 48;
    pp[lane] = blend0 * eA0 / sA + blend1 * eB0 / sB;
    if (v1ok) pp[d1] = blend0 * eA1 / sA + blend1 * eB1 / sB;
}

// ================= out = attn @ v -> transposed bf16 hi/lo =================
__global__ void attnv(const float* __restrict__ probs, const float* __restrict__ qkv2,
                      __nv_bfloat16* __restrict__ th, __nv_bfloat16* __restrict__ tl) {
    __shared__ float a_s[2304];
    const int h = blockIdx.y, b = blockIdx.z;
    const int n = blockIdx.x * 128 + threadIdx.x;
    const float* ap = probs + (size_t)(b * NHEADS + h) * 2304;
    for (int i = threadIdx.x; i < 2304; i += 128) a_s[i] = ap[i];
    __syncthreads();
    const float* vbase = qkv2 + ((size_t)b * C3 + 768 + h * CPH) * NPIX + n;
    float vr[48];
#pragma unroll
    for (int d = 0; d < 48; d++) vr[d] = vbase[(size_t)d * NPIX];
    size_t obase = ((size_t)b * NPIX + n) * CDIM + h * CPH;
#pragma unroll 4
    for (int c = 0; c < 48; c++) {
        float acc = 0.f;
#pragma unroll
        for (int d = 0; d < 48; d++) acc += a_s[c * 48 + d] * vr[d];
        __nv_bfloat16 hi = __float2bfloat16_rn(acc);
        th[obase + c] = hi;
        tl[obase + c] = __float2bfloat16_rn(acc - __bfloat162float(hi));
    }
}

// ================= launch =================
extern "C" void kernel_launch(void* const* d_in, const int* in_sizes, int n_in,
                              void* d_out, int out_size) {
    const float* x           = (const float*)d_in[0];
    const int*   mask        = (const int*)d_in[1];
    const float* qkv_w       = (const float*)d_in[2];
    const float* dw_w        = (const float*)d_in[3];
    const float* proj_w      = (const float*)d_in[4];
    const float* temperature = (const float*)d_in[5];
    const float* w_blend     = (const float*)d_in[6];
    const float* pos_w1      = (const float*)d_in[7];
    const float* pos_w2      = (const float*)d_in[8];
    float* out = (float*)d_out;

    float *qkv1, *qkv2, *norm, *part, *logits, *probs, *pos1;
    __nv_bfloat16 *xh, *xl, *ah, *al, *wqh, *wql, *wph, *wpl;
    cudaGetSymbolAddress((void**)&qkv1, g_qkv1);
    cudaGetSymbolAddress((void**)&qkv2, g_qkv2);
    cudaGetSymbolAddress((void**)&norm, g_norm);
    cudaGetSymbolAddress((void**)&part, g_part);
    cudaGetSymbolAddress((void**)&logits, g_logits);
    cudaGetSymbolAddress((void**)&probs, g_probs);
    cudaGetSymbolAddress((void**)&pos1, g_pos1);
    cudaGetSymbolAddress((void**)&xh, g_xT_hi);
    cudaGetSymbolAddress((void**)&xl, g_xT_lo);
    cudaGetSymbolAddress((void**)&ah, g_aT_hi);
    cudaGetSymbolAddress((void**)&al, g_aT_lo);
    cudaGetSymbolAddress((void**)&wqh, g_wq_hi);
    cudaGetSymbolAddress((void**)&wql, g_wq_lo);
    cudaGetSymbolAddress((void**)&wph, g_wp_hi);
    cudaGetSymbolAddress((void**)&wpl, g_wp_lo);

    static bool attr_set = false;
    if (!attr_set) {
        cudaFuncSetAttribute(gemm_hmma, cudaFuncAttributeMaxDynamicSharedMemorySize, GEMM_SMEM);
        attr_set = true;
    }

    // 0) operand conversion
    cvt_split<<<(C3 * CDIM + 255) / 256, 256>>>(qkv_w, wqh, wql, C3 * CDIM);
    cvt_split<<<(CDIM * CDIM + 255) / 256, 256>>>(proj_w, wph, wpl, CDIM * CDIM);
    transpose_split<<<dim3(NPIX / 32, CDIM / 32, BATCH), dim3(32, 32)>>>(x, xh, xl);

    // 1) qkv 1x1 conv via HMMA (grid: m-tiles fastest for B-tile L2 reuse)
    gemm_hmma<<<dim3(C3 / 128, NPIX / 128, BATCH), 256, GEMM_SMEM>>>(
        wqh, wql, xh, xl, qkv1, (size_t)NPIX * CDIM, (size_t)C3 * NPIX);

    // 2) depthwise 3x3
    {
        int total = BATCH * C3 * NPIX;
        dwconv3x3<0><<<(total + 255) / 256, 256>>>(
            qkv1, dw_w, qkv2, C3, (size_t)C3 * NPIX, (size_t)C3 * NPIX, total);
    }

    // 3) q,k row norms
    rownorm_kernel<<<BATCH * 768, 256>>>(qkv2, norm);

    // 4) q.k^T + reduce
    attn_partial<<<dim3(16, NHEADS, BATCH), 256>>>(qkv2, part);
    attn_reduce<<<(32 * 2304 + 255) / 256, 256>>>(part, norm, temperature, logits);

    // 5) dual softmax blend
    softmax_blend<<<BATCH * NHEADS * 48, 32>>>(logits, mask, w_blend, probs);

    // 6) attn @ v -> transposed bf16 hi/lo
    attnv<<<dim3(NPIX / 128, NHEADS, BATCH), 128>>>(probs, qkv2, ah, al);

    // 7) proj 1x1 conv via HMMA (writes full d_out)
    gemm_hmma<<<dim3(CDIM / 128, NPIX / 128, BATCH), 256, GEMM_SMEM>>>(
        wph, wpl, ah, al, out, (size_t)NPIX * CDIM, (size_t)CDIM * NPIX);

    // 8) pos path added into d_out
    {
        int total = BATCH * CDIM * NPIX;
        dwconv3x3<1><<<(total + 255) / 256, 256>>>(
            qkv2 + (size_t)768 * NPIX, pos_w1, pos1, CDIM,
            (size_t)C3 * NPIX, (size_t)CDIM * NPIX, total);
        dwconv3x3<2><<<(total + 255) / 256, 256>>>(
            pos1, pos_w2, out, CDIM,
            (size_t)CDIM * NPIX, (size_t)CDIM * NPIX, total);
    }
}

// round 4
// speedup vs baseline: 1.6356x; 1.3262x over previous
#include <cuda_runtime.h>
#include <cuda_bf16.h>
#include <math.h>
#include <cstdint>

#define BATCH 4
#define CDIM 384
#define NHEADS 8
#define CPH 48
#define NPIX 16384
#define C3 1152

// ================= scratch (static device globals; no allocation) =================
__device__ float g_qkv1[(size_t)BATCH * C3 * NPIX];
__device__ float g_qkv2[(size_t)BATCH * C3 * NPIX];
__device__ float g_norm[BATCH * 768];
__device__ float g_part[32 * 16 * 2304];
__device__ float g_logits[32 * 2304];
__device__ float g_probs[32 * 2304];
__device__ float g_pos1[(size_t)BATCH * CDIM * NPIX];
__device__ __nv_bfloat16 g_xT_hi[(size_t)BATCH * NPIX * CDIM];
__device__ __nv_bfloat16 g_xT_lo[(size_t)BATCH * NPIX * CDIM];
__device__ __nv_bfloat16 g_aT_hi[(size_t)BATCH * NPIX * CDIM];
__device__ __nv_bfloat16 g_aT_lo[(size_t)BATCH * NPIX * CDIM];
__device__ __nv_bfloat16 g_wq_hi[C3 * CDIM];
__device__ __nv_bfloat16 g_wq_lo[C3 * CDIM];
__device__ __nv_bfloat16 g_wp_hi[CDIM * CDIM];
__device__ __nv_bfloat16 g_wp_lo[CDIM * CDIM];

// ================= helpers =================
__device__ __forceinline__ uint32_t smem_u32(const void* p) {
    uint32_t a;
    asm("{ .reg .u64 t; cvta.to.shared.u64 t, %1; cvt.u32.u64 %0, t; }" : "=r"(a) : "l"(p));
    return a;
}
__device__ __forceinline__ void cp16(uint32_t s, const void* g) {
    asm volatile("cp.async.cg.shared.global [%0], [%1], 16;" :: "r"(s), "l"(g));
}
__device__ __forceinline__ void mma16816(float* c, const uint32_t* a, uint32_t b0, uint32_t b1) {
    asm volatile(
        "mma.sync.aligned.m16n8k16.row.col.f32.bf16.bf16.f32 "
        "{%0,%1,%2,%3}, {%4,%5,%6,%7}, {%8,%9}, {%0,%1,%2,%3};"
        : "+f"(c[0]), "+f"(c[1]), "+f"(c[2]), "+f"(c[3])
        : "r"(a[0]), "r"(a[1]), "r"(a[2]), "r"(a[3]), "r"(b0), "r"(b1));
}

// ================= 3xBF16 HMMA GEMM =================
// CTA tile 128x128, 8 warps (warp tile 32x64), K chunks of 32, double buffer, 2 CTAs/SM.
#define TILE_B 10240
#define BUF_B 40960
#define GEMM_SMEM (2 * BUF_B)

__global__ void __launch_bounds__(256, 2) gemm_hmma(
    const __nv_bfloat16* __restrict__ Ah, const __nv_bfloat16* __restrict__ Al,
    const __nv_bfloat16* __restrict__ Bh, const __nv_bfloat16* __restrict__ Bl,
    float* __restrict__ C, size_t strideB, size_t strideC) {
    extern __shared__ char sm[];
    const uint32_t sb = smem_u32(sm);
    const int tid = threadIdx.x;
    const int m0 = blockIdx.x * 128;
    const int n0 = blockIdx.y * 128;
    const __nv_bfloat16* bhp = Bh + blockIdx.z * strideB;
    const __nv_bfloat16* blp = Bl + blockIdx.z * strideB;
    float* Cp = C + blockIdx.z * strideC;

    const int wid = tid >> 5, lane = tid & 31;
    const int wm = (wid & 3) * 32, wn = (wid >> 2) * 64;
    const int qr = lane >> 2, qc = lane & 3;

    float acc[2][8][4];
#pragma unroll
    for (int i = 0; i < 2; i++)
#pragma unroll
        for (int j = 0; j < 8; j++)
#pragma unroll
            for (int t = 0; t < 4; t++) acc[i][j][t] = 0.f;

    const int row0 = tid >> 2, c40 = tid & 3;
    const int row1 = (tid + 256) >> 2;

    auto issue = [&](int ch, int b) {
        const int k0 = ch * 32;
        const uint32_t bb = sb + b * BUF_B;
        {
            uint32_t so = row0 * 80 + c40 * 16;
            cp16(bb + so, (const char*)(Ah + (size_t)(m0 + row0) * 384 + k0) + c40 * 16);
            cp16(bb + TILE_B + so, (const char*)(Al + (size_t)(m0 + row0) * 384 + k0) + c40 * 16);
            cp16(bb + 2 * TILE_B + so, (const char*)(bhp + (size_t)(n0 + row0) * 384 + k0) + c40 * 16);
            cp16(bb + 3 * TILE_B + so, (const char*)(blp + (size_t)(n0 + row0) * 384 + k0) + c40 * 16);
        }
        {
            uint32_t so = row1 * 80 + c40 * 16;
            cp16(bb + so, (const char*)(Ah + (size_t)(m0 + row1) * 384 + k0) + c40 * 16);
            cp16(bb + TILE_B + so, (const char*)(Al + (size_t)(m0 + row1) * 384 + k0) + c40 * 16);
            cp16(bb + 2 * TILE_B + so, (const char*)(bhp + (size_t)(n0 + row1) * 384 + k0) + c40 * 16);
            cp16(bb + 3 * TILE_B + so, (const char*)(blp + (size_t)(n0 + row1) * 384 + k0) + c40 * 16);
        }
        asm volatile("cp.async.commit_group;");
    };

    issue(0, 0);

#pragma unroll 1
    for (int ch = 0; ch < 12; ch++) {
        if (ch < 11) {
            issue(ch + 1, (ch + 1) & 1);
            asm volatile("cp.async.wait_group 1;");
        } else {
            asm volatile("cp.async.wait_group 0;");
        }
        __syncthreads();

        const char* buf = sm + (ch & 1) * BUF_B;
#pragma unroll
        for (int kc = 0; kc < 32; kc += 16) {
            uint32_t aH[2][4], aL[2][4];
#pragma unroll
            for (int i = 0; i < 2; i++) {
                uint32_t o = (uint32_t)(wm + i * 16 + qr) * 80 + (uint32_t)(kc + qc * 2) * 2;
                aH[i][0] = *(const uint32_t*)(buf + o);
                aH[i][1] = *(const uint32_t*)(buf + o + 640);
                aH[i][2] = *(const uint32_t*)(buf + o + 16);
                aH[i][3] = *(const uint32_t*)(buf + o + 656);
                aL[i][0] = *(const uint32_t*)(buf + TILE_B + o);
                aL[i][1] = *(const uint32_t*)(buf + TILE_B + o + 640);
                aL[i][2] = *(const uint32_t*)(buf + TILE_B + o + 16);
                aL[i][3] = *(const uint32_t*)(buf + TILE_B + o + 656);
            }
#pragma unroll
            for (int j = 0; j < 8; j++) {
                uint32_t ob = (uint32_t)(wn + j * 8 + qr) * 80 + (uint32_t)(kc + qc * 2) * 2;
                uint32_t bh0 = *(const uint32_t*)(buf + 2 * TILE_B + ob);
                uint32_t bh1 = *(const uint32_t*)(buf + 2 * TILE_B + ob + 16);
                uint32_t bl0 = *(const uint32_t*)(buf + 3 * TILE_B + ob);
                uint32_t bl1 = *(const uint32_t*)(buf + 3 * TILE_B + ob + 16);
#pragma unroll
                for (int i = 0; i < 2; i++) {
                    mma16816(acc[i][j], aH[i], bh0, bh1);
                    mma16816(acc[i][j], aH[i], bl0, bl1);
                    mma16816(acc[i][j], aL[i], bh0, bh1);
                }
            }
        }
        __syncthreads();
    }

#pragma unroll
    for (int i = 0; i < 2; i++) {
        int r0 = m0 + wm + i * 16 + qr;
#pragma unroll
        for (int j = 0; j < 8; j++) {
            int cc = n0 + wn + j * 8 + qc * 2;
            float* cp = Cp + (size_t)r0 * NPIX + cc;
            *(float2*)cp = make_float2(acc[i][j][0], acc[i][j][1]);
            *(float2*)(cp + (size_t)8 * NPIX) = make_float2(acc[i][j][2], acc[i][j][3]);
        }
    }
}

// ================= fp32 -> bf16 hi/lo converters =================
__global__ void cvt_split(const float* __restrict__ in, __nv_bfloat16* __restrict__ hi,
                          __nv_bfloat16* __restrict__ lo, int n) {
    int i = blockIdx.x * 256 + threadIdx.x;
    if (i >= n) return;
    float v = in[i];
    __nv_bfloat16 h = __float2bfloat16_rn(v);
    hi[i] = h;
    lo[i] = __float2bfloat16_rn(v - __bfloat162float(h));
}

__global__ void transpose_split(const float* __restrict__ x, __nv_bfloat16* __restrict__ th,
                                __nv_bfloat16* __restrict__ tl) {
    __shared__ float t[32][33];
    int b = blockIdx.z;
    int n0 = blockIdx.x * 32, c0 = blockIdx.y * 32;
    t[threadIdx.y][threadIdx.x] =
        x[((size_t)b * CDIM + c0 + threadIdx.y) * NPIX + n0 + threadIdx.x];
    __syncthreads();
    float v = t[threadIdx.x][threadIdx.y];
    __nv_bfloat16 h = __float2bfloat16_rn(v);
    size_t o = ((size_t)b * NPIX + n0 + threadIdx.y) * CDIM + c0 + threadIdx.x;
    th[o] = h;
    tl[o] = __float2bfloat16_rn(v - __bfloat162float(h));
}

// ================= vectorized depthwise 3x3, SAME (4 outputs per thread) =================
// MODE 0: write; MODE 1: gelu write; MODE 2: add into out
template <int MODE>
__global__ void dwconv3x3v(const float* __restrict__ in, const float* __restrict__ w,
                           float* __restrict__ out, int CH,
                           size_t inStride, size_t outStride, int totalq) {
    int idx = blockIdx.x * 256 + threadIdx.x;
    if (idx >= totalq) return;
    int x4 = (idx & 31) * 4;
    int y = (idx >> 5) & 127;
    int ch = (idx >> 12) % CH;
    int b = idx / (CH << 12);
    const float* ip = in + (size_t)b * inStride + (size_t)ch * NPIX;
    const float* wp = w + ch * 9;
    float w00 = wp[0], w01 = wp[1], w02 = wp[2];
    float w10 = wp[3], w11 = wp[4], w12 = wp[5];
    float w20 = wp[6], w21 = wp[7], w22 = wp[8];

    float o0 = 0.f, o1 = 0.f, o2 = 0.f, o3 = 0.f;
#pragma unroll
    for (int ky = 0; ky < 3; ky++) {
        int yy = y + ky - 1;
        if (yy < 0 || yy > 127) continue;
        const float* rp = ip + yy * 128;
        float4 c = *(const float4*)(rp + x4);
        float lft = (x4 > 0) ? rp[x4 - 1] : 0.f;
        float rgt = (x4 < 124) ? rp[x4 + 4] : 0.f;
        float wa = (ky == 0) ? w00 : (ky == 1) ? w10 : w20;
        float wb = (ky == 0) ? w01 : (ky == 1) ? w11 : w21;
        float wc = (ky == 0) ? w02 : (ky == 1) ? w12 : w22;
        o0 += wa * lft + wb * c.x + wc * c.y;
        o1 += wa * c.x + wb * c.y + wc * c.z;
        o2 += wa * c.y + wb * c.z + wc * c.w;
        o3 += wa * c.z + wb * c.w + wc * rgt;
    }
    // SAME-padding edge zeroing is handled by lft/rgt = 0 above.
    float* op = out + (size_t)b * outStride + (size_t)ch * NPIX + y * 128 + x4;
    if (MODE == 0) {
        *(float4*)op = make_float4(o0, o1, o2, o3);
    } else if (MODE == 1) {
        float4 r;
        r.x = 0.5f * o0 * (1.0f + erff(o0 * 0.70710678118654752f));
        r.y = 0.5f * o1 * (1.0f + erff(o1 * 0.70710678118654752f));
        r.z = 0.5f * o2 * (1.0f + erff(o2 * 0.70710678118654752f));
        r.w = 0.5f * o3 * (1.0f + erff(o3 * 0.70710678118654752f));
        *(float4*)op = r;
    } else {
        float4 prev = *(const float4*)op;
        *(float4*)op = make_float4(prev.x + o0, prev.y + o1, prev.z + o2, prev.w + o3);
    }
}

// ================= per-row inverse L2 norms (float4) =================
__global__ void rownorm_kernel(const float* __restrict__ qk, float* __restrict__ invn) {
    int row = blockIdx.x;
    int b = row / 768, c = row % 768;
    const float* p = qk + ((size_t)b * C3 + c) * NPIX;
    float s = 0.f;
    for (int i = threadIdx.x; i < NPIX / 4; i += 256) {
        float4 v = *((const float4*)p + i);
        s += v.x * v.x + v.y * v.y + v.z * v.z + v.w * v.w;
    }
    __shared__ float red[8];
#pragma unroll
    for (int o = 16; o; o >>= 1) s += __shfl_down_sync(~0u, s, o);
    if ((threadIdx.x & 31) == 0) red[threadIdx.x >> 5] = s;
    __syncthreads();
    if (threadIdx.x < 8) {
        s = red[threadIdx.x];
#pragma unroll
        for (int o = 4; o; o >>= 1) s += __shfl_down_sync(0xffu, s, o);
        if (threadIdx.x == 0) invn[row] = 1.0f / fmaxf(sqrtf(s), 1e-12f);
    }
}

// ================= q.k^T partials =================
__global__ void attn_partial(const float* __restrict__ qkv, float* __restrict__ part) {
    __shared__ float qs[48][65];
    __shared__ float ks[48][65];
    const int split = blockIdx.x, h = blockIdx.y, b = blockIdx.z;
    const int tid = threadIdx.x;
    const float* qbase = qkv + ((size_t)b * C3 + h * CPH) * NPIX;
    const float* kbase = qkv + ((size_t)b * C3 + 384 + h * CPH) * NPIX;
    const int tx = tid & 15, ty = tid >> 4;
    const int c0 = ty * 3, d0 = tx * 3;
    float acc[3][3];
#pragma unroll
    for (int i = 0; i < 3; i++)
#pragma unroll
        for (int j = 0; j < 3; j++) acc[i][j] = 0.f;

    for (int chunk = 0; chunk < 16; chunk++) {
        int n0 = split * 1024 + chunk * 64;
        __syncthreads();
#pragma unroll
        for (int r = 0; r < 3; r++) {
            int v = tid + r * 256;
            int row = v >> 4;
            int col = (v & 15) << 2;
            float4 q4 = *(const float4*)(qbase + (size_t)row * NPIX + n0 + col);
            qs[row][col] = q4.x; qs[row][col + 1] = q4.y;
            qs[row][col + 2] = q4.z; qs[row][col + 3] = q4.w;
            float4 k4 = *(const float4*)(kbase + (size_t)row * NPIX + n0 + col);
            ks[row][col] = k4.x; ks[row][col + 1] = k4.y;
            ks[row][col + 2] = k4.z; ks[row][col + 3] = k4.w;
        }
        __syncthreads();
#pragma unroll 16
        for (int i = 0; i < 64; i++) {
            float q0 = qs[c0][i], q1 = qs[c0 + 1][i], q2 = qs[c0 + 2][i];
            float k0v = ks[d0][i], k1v = ks[d0 + 1][i], k2v = ks[d0 + 2][i];
            acc[0][0] += q0 * k0v; acc[0][1] += q0 * k1v; acc[0][2] += q0 * k2v;
            acc[1][0] += q1 * k0v; acc[1][1] += q1 * k1v; acc[1][2] += q1 * k2v;
            acc[2][0] += q2 * k0v; acc[2][1] += q2 * k1v; acc[2][2] += q2 * k2v;
        }
    }
    float* pp = part + ((size_t)((b * NHEADS + h) * 16 + split)) * 2304;
#pragma unroll
    for (int i = 0; i < 3; i++)
#pragma unroll
        for (int j = 0; j < 3; j++) pp[(c0 + i) * 48 + d0 + j] = acc[i][j];
}

__global__ void attn_reduce(const float* __restrict__ part, const float* __restrict__ invn,
                            const float* __restrict__ temp, float* __restrict__ logits) {
    int idx = blockIdx.x * 256 + threadIdx.x;
    if (idx >= 32 * 2304) return;
    int bh = idx / 2304, o = idx % 2304;
    int b = bh / NHEADS, h = bh % NHEADS;
    int c = o / 48, d = o % 48;
    float s = 0.f;
#pragma unroll
    for (int sp = 0; sp < 16; sp++) s += part[((size_t)bh * 16 + sp) * 2304 + o];
    float inq = invn[b * 768 + h * CPH + c];
    float ink = invn[b * 768 + 384 + h * CPH + d];
    logits[idx] = s * inq * ink * temp[h];
}

__global__ void softmax_blend(const float* __restrict__ logits, const int* __restrict__ mask,
                              const float* __restrict__ wb, float* __restrict__ probs) {
    int row = blockIdx.x;
    int c = row % 48;
    int h = (row / 48) % NHEADS;
    int lane = threadIdx.x;
    int d1 = lane + 32;
    const float* lp = logits + (size_t)row * 48;
    const int* mp = mask + (h * 48 + c) * 48;
    bool v1ok = d1 < 48;
    float a0 = lp[lane];
    float a1 = v1ok ? lp[d1] : -INFINITY;
    float b0 = (mp[lane] == 0) ? -1e9f : a0;
    float b1 = v1ok ? ((mp[d1] == 0) ? -1e9f : a1) : -INFINITY;
    float mA = fmaxf(a0, a1), mB = fmaxf(b0, b1);
#pragma unroll
    for (int o = 16; o; o >>= 1) {
        mA = fmaxf(mA, __shfl_xor_sync(~0u, mA, o));
        mB = fmaxf(mB, __shfl_xor_sync(~0u, mB, o));
    }
    float eA0 = expf(a0 - mA);
    float eA1 = v1ok ? expf(a1 - mA) : 0.f;
    float eB0 = expf(b0 - mB);
    float eB1 = v1ok ? expf(b1 - mB) : 0.f;
    float sA = eA0 + eA1, sB = eB0 + eB1;
#pragma unroll
    for (int o = 16; o; o >>= 1) {
        sA += __shfl_xor_sync(~0u, sA, o);
        sB += __shfl_xor_sync(~0u, sB, o);
    }
    float w0 = wb[0], w1 = wb[1];
    float wm = fmaxf(w0, w1);
    float ew0 = expf(w0 - wm), ew1 = expf(w1 - wm);
    float wsum = ew0 + ew1;
    float blend0 = ew0 / wsum, blend1 = ew1 / wsum;
    float* pp = probs + (size_t)row * 48;
    pp[lane] = blend0 * eA0 / sA + blend1 * eB0 / sB;
    if (v1ok) pp[d1] = blend0 * eA1 / sA + blend1 * eB1 / sB;
}

// ================= out = attn @ v -> transposed bf16 hi/lo =================
__global__ void attnv(const float* __restrict__ probs, const float* __restrict__ qkv2,
                      __nv_bfloat16* __restrict__ th, __nv_bfloat16* __restrict__ tl) {
    __shared__ float a_s[2304];
    const int h = blockIdx.y, b = blockIdx.z;
    const int n = blockIdx.x * 128 + threadIdx.x;
    const float* ap = probs + (size_t)(b * NHEADS + h) * 2304;
    for (int i = threadIdx.x; i < 2304; i += 128) a_s[i] = ap[i];
    __syncthreads();
    const float* vbase = qkv2 + ((size_t)b * C3 + 768 + h * CPH) * NPIX + n;
    float vr[48];
#pragma unroll
    for (int d = 0; d < 48; d++) vr[d] = vbase[(size_t)d * NPIX];
    size_t obase = ((size_t)b * NPIX + n) * CDIM + h * CPH;
#pragma unroll 4
    for (int c = 0; c < 48; c++) {
        float acc = 0.f;
#pragma unroll
        for (int d = 0; d < 48; d++) acc += a_s[c * 48 + d] * vr[d];
        __nv_bfloat16 hi = __float2bfloat16_rn(acc);
        th[obase + c] = hi;
        tl[obase + c] = __float2bfloat16_rn(acc - __bfloat162float(hi));
    }
}

// ================= launch =================
extern "C" void kernel_launch(void* const* d_in, const int* in_sizes, int n_in,
                              void* d_out, int out_size) {
    const float* x           = (const float*)d_in[0];
    const int*   mask        = (const int*)d_in[1];
    const float* qkv_w       = (const float*)d_in[2];
    const float* dw_w        = (const float*)d_in[3];
    const float* proj_w      = (const float*)d_in[4];
    const float* temperature = (const float*)d_in[5];
    const float* w_blend     = (const float*)d_in[6];
    const float* pos_w1      = (const float*)d_in[7];
    const float* pos_w2      = (const float*)d_in[8];
    float* out = (float*)d_out;

    float *qkv1, *qkv2, *norm, *part, *logits, *probs, *pos1;
    __nv_bfloat16 *xh, *xl, *ah, *al, *wqh, *wql, *wph, *wpl;
    cudaGetSymbolAddress((void**)&qkv1, g_qkv1);
    cudaGetSymbolAddress((void**)&qkv2, g_qkv2);
    cudaGetSymbolAddress((void**)&norm, g_norm);
    cudaGetSymbolAddress((void**)&part, g_part);
    cudaGetSymbolAddress((void**)&logits, g_logits);
    cudaGetSymbolAddress((void**)&probs, g_probs);
    cudaGetSymbolAddress((void**)&pos1, g_pos1);
    cudaGetSymbolAddress((void**)&xh, g_xT_hi);
    cudaGetSymbolAddress((void**)&xl, g_xT_lo);
    cudaGetSymbolAddress((void**)&ah, g_aT_hi);
    cudaGetSymbolAddress((void**)&al, g_aT_lo);
    cudaGetSymbolAddress((void**)&wqh, g_wq_hi);
    cudaGetSymbolAddress((void**)&wql, g_wq_lo);
    cudaGetSymbolAddress((void**)&wph, g_wp_hi);
    cudaGetSymbolAddress((void**)&wpl, g_wp_lo);

    static bool attr_set = false;
    if (!attr_set) {
        cudaFuncSetAttribute(gemm_hmma, cudaFuncAttributeMaxDynamicSharedMemorySize, GEMM_SMEM);
        attr_set = true;
    }

    // 0) operand conversion
    cvt_split<<<(C3 * CDIM + 255) / 256, 256>>>(qkv_w, wqh, wql, C3 * CDIM);
    cvt_split<<<(CDIM * CDIM + 255) / 256, 256>>>(proj_w, wph, wpl, CDIM * CDIM);
    transpose_split<<<dim3(NPIX / 32, CDIM / 32, BATCH), dim3(32, 32)>>>(x, xh, xl);

    // 1) qkv 1x1 conv via HMMA
    gemm_hmma<<<dim3(C3 / 128, NPIX / 128, BATCH), 256, GEMM_SMEM>>>(
        wqh, wql, xh, xl, qkv1, (size_t)NPIX * CDIM, (size_t)C3 * NPIX);

    // 2) depthwise 3x3 (vectorized)
    {
        int totalq = BATCH * C3 * NPIX / 4;
        dwconv3x3v<0><<<(totalq + 255) / 256, 256>>>(
            qkv1, dw_w, qkv2, C3, (size_t)C3 * NPIX, (size_t)C3 * NPIX, totalq);
    }

    // 3) q,k row norms
    rownorm_kernel<<<BATCH * 768, 256>>>(qkv2, norm);

    // 4) q.k^T + reduce
    attn_partial<<<dim3(16, NHEADS, BATCH), 256>>>(qkv2, part);
    attn_reduce<<<(32 * 2304 + 255) / 256, 256>>>(part, norm, temperature, logits);

    // 5) dual softmax blend
    softmax_blend<<<BATCH * NHEADS * 48, 32>>>(logits, mask, w_blend, probs);

    // 6) attn @ v -> transposed bf16 hi/lo
    attnv<<<dim3(NPIX / 128, NHEADS, BATCH), 128>>>(probs, qkv2, ah, al);

    // 7) proj 1x1 conv via HMMA
    gemm_hmma<<<dim3(CDIM / 128, NPIX / 128, BATCH), 256, GEMM_SMEM>>>(
        wph, wpl, ah, al, out, (size_t)NPIX * CDIM, (size_t)CDIM * NPIX);

    // 8) pos path added into d_out (vectorized)
    {
        int totalq = BATCH * CDIM * NPIX / 4;
        dwconv3x3v<1><<<(totalq + 255) / 256, 256>>>(
            qkv2 + (size_t)768 * NPIX, pos_w1, pos1, CDIM,
            (size_t)C3 * NPIX, (size_t)CDIM * NPIX, totalq);
        dwconv3x3v<2><<<(totalq + 255) / 256, 256>>>(
            pos1, pos_w2, out, CDIM,
            (size_t)CDIM * NPIX, (size_t)CDIM * NPIX, totalq);
    }
}

// round 5
// speedup vs baseline: 2.1135x; 1.2922x over previous
#include <cuda_runtime.h>
#include <cuda_bf16.h>
#include <math.h>
#include <cstdint>

#define BATCH 4
#define CDIM 384
#define NHEADS 8
#define CPH 48
#define NPIX 16384
#define C3 1152

// ================= scratch (static device globals; no allocation) =================
__device__ float g_qkv1[(size_t)BATCH * C3 * NPIX];
__device__ float g_qkv2[(size_t)BATCH * C3 * NPIX];
__device__ float g_norm[BATCH * 768];
__device__ float g_part[32 * 16 * 2304];
__device__ float g_logits[32 * 2304];
__device__ float g_probs[32 * 2304];
__device__ float g_pos1[(size_t)BATCH * CDIM * NPIX];
__device__ __nv_bfloat16 g_xT_hi[(size_t)BATCH * NPIX * CDIM];
__device__ __nv_bfloat16 g_xT_lo[(size_t)BATCH * NPIX * CDIM];
__device__ __nv_bfloat16 g_aT_hi[(size_t)BATCH * NPIX * CDIM];
__device__ __nv_bfloat16 g_aT_lo[(size_t)BATCH * NPIX * CDIM];
__device__ __nv_bfloat16 g_wq_hi[C3 * CDIM];
__device__ __nv_bfloat16 g_wq_lo[C3 * CDIM];
__device__ __nv_bfloat16 g_wp_hi[CDIM * CDIM];
__device__ __nv_bfloat16 g_wp_lo[CDIM * CDIM];

// ================= helpers =================
__device__ __forceinline__ uint32_t smem_u32(const void* p) {
    uint32_t a;
    asm("{ .reg .u64 t; cvta.to.shared.u64 t, %1; cvt.u32.u64 %0, t; }" : "=r"(a) : "l"(p));
    return a;
}
__device__ __forceinline__ void cp16(uint32_t s, const void* g) {
    asm volatile("cp.async.cg.shared.global [%0], [%1], 16;" :: "r"(s), "l"(g));
}
__device__ __forceinline__ void mma16816(float* c, const uint32_t* a, uint32_t b0, uint32_t b1) {
    asm volatile(
        "mma.sync.aligned.m16n8k16.row.col.f32.bf16.bf16.f32 "
        "{%0,%1,%2,%3}, {%4,%5,%6,%7}, {%8,%9}, {%0,%1,%2,%3};"
        : "+f"(c[0]), "+f"(c[1]), "+f"(c[2]), "+f"(c[3])
        : "r"(a[0]), "r"(a[1]), "r"(a[2]), "r"(a[3]), "r"(b0), "r"(b1));
}
__device__ __forceinline__ void ldsm4(uint32_t* r, uint32_t addr) {
    asm volatile("ldmatrix.sync.aligned.m8n8.x4.shared.b16 {%0,%1,%2,%3}, [%4];"
                 : "=r"(r[0]), "=r"(r[1]), "=r"(r[2]), "=r"(r[3]) : "r"(addr));
}

// ================= 3xBF16 HMMA GEMM (ldmatrix fragment loads) =================
// CTA tile 128x128, 8 warps (warp tile 32x64), K chunks of 32, double buffer, 2 CTAs/SM.
#define TILE_B 10240
#define BUF_B 40960
#define GEMM_SMEM (2 * BUF_B)

__global__ void __launch_bounds__(256, 2) gemm_hmma(
    const __nv_bfloat16* __restrict__ Ah, const __nv_bfloat16* __restrict__ Al,
    const __nv_bfloat16* __restrict__ Bh, const __nv_bfloat16* __restrict__ Bl,
    float* __restrict__ C, size_t strideB, size_t strideC) {
    extern __shared__ char sm[];
    const uint32_t sb = smem_u32(sm);
    const int tid = threadIdx.x;
    const int m0 = blockIdx.x * 128;
    const int n0 = blockIdx.y * 128;
    const __nv_bfloat16* bhp = Bh + blockIdx.z * strideB;
    const __nv_bfloat16* blp = Bl + blockIdx.z * strideB;
    float* Cp = C + blockIdx.z * strideC;

    const int wid = tid >> 5, lane = tid & 31;
    const int wm = (wid & 3) * 32, wn = (wid >> 2) * 64;
    const int qr = lane >> 2, qc = lane & 3;
    // ldmatrix per-lane address components
    const int la = lane & 15, ha = lane >> 4;          // A: rows 0-15, col half
    const int lb = (lane & 7) + (lane >> 4) * 8;       // B: row within 16
    const int mb = (lane >> 3) & 1;                    // B: col half

    float acc[2][8][4];
#pragma unroll
    for (int i = 0; i < 2; i++)
#pragma unroll
        for (int j = 0; j < 8; j++)
#pragma unroll
            for (int t = 0; t < 4; t++) acc[i][j][t] = 0.f;

    const int row0 = tid >> 2, c40 = tid & 3;
    const int row1 = (tid + 256) >> 2;

    auto issue = [&](int ch, int b) {
        const int k0 = ch * 32;
        const uint32_t bb = sb + b * BUF_B;
        {
            uint32_t so = row0 * 80 + c40 * 16;
            cp16(bb + so, (const char*)(Ah + (size_t)(m0 + row0) * 384 + k0) + c40 * 16);
            cp16(bb + TILE_B + so, (const char*)(Al + (size_t)(m0 + row0) * 384 + k0) + c40 * 16);
            cp16(bb + 2 * TILE_B + so, (const char*)(bhp + (size_t)(n0 + row0) * 384 + k0) + c40 * 16);
            cp16(bb + 3 * TILE_B + so, (const char*)(blp + (size_t)(n0 + row0) * 384 + k0) + c40 * 16);
        }
        {
            uint32_t so = row1 * 80 + c40 * 16;
            cp16(bb + so, (const char*)(Ah + (size_t)(m0 + row1) * 384 + k0) + c40 * 16);
            cp16(bb + TILE_B + so, (const char*)(Al + (size_t)(m0 + row1) * 384 + k0) + c40 * 16);
            cp16(bb + 2 * TILE_B + so, (const char*)(bhp + (size_t)(n0 + row1) * 384 + k0) + c40 * 16);
            cp16(bb + 3 * TILE_B + so, (const char*)(blp + (size_t)(n0 + row1) * 384 + k0) + c40 * 16);
        }
        asm volatile("cp.async.commit_group;");
    };

    issue(0, 0);

#pragma unroll 1
    for (int ch = 0; ch < 12; ch++) {
        if (ch < 11) {
            issue(ch + 1, (ch + 1) & 1);
            asm volatile("cp.async.wait_group 1;");
        } else {
            asm volatile("cp.async.wait_group 0;");
        }
        __syncthreads();

        const uint32_t bufb = sb + (ch & 1) * BUF_B;
#pragma unroll
        for (int kc = 0; kc < 32; kc += 16) {
            uint32_t aH[2][4], aL[2][4];
#pragma unroll
            for (int i = 0; i < 2; i++) {
                uint32_t ar = (uint32_t)(wm + i * 16 + la) * 80 + (uint32_t)(kc + ha * 8) * 2;
                ldsm4(aH[i], bufb + ar);
                ldsm4(aL[i], bufb + TILE_B + ar);
            }
#pragma unroll
            for (int jp = 0; jp < 4; jp++) {
                uint32_t br = (uint32_t)(wn + jp * 16 + lb) * 80 + (uint32_t)(kc + mb * 8) * 2;
                uint32_t bh[4], bl[4];
                ldsm4(bh, bufb + 2 * TILE_B + br);
                ldsm4(bl, bufb + 3 * TILE_B + br);
#pragma unroll
                for (int i = 0; i < 2; i++) {
                    mma16816(acc[i][jp * 2], aH[i], bh[0], bh[1]);
                    mma16816(acc[i][jp * 2], aH[i], bl[0], bl[1]);
                    mma16816(acc[i][jp * 2], aL[i], bh[0], bh[1]);
                    mma16816(acc[i][jp * 2 + 1], aH[i], bh[2], bh[3]);
                    mma16816(acc[i][jp * 2 + 1], aH[i], bl[2], bl[3]);
                    mma16816(acc[i][jp * 2 + 1], aL[i], bh[2], bh[3]);
                }
            }
        }
        __syncthreads();
    }

#pragma unroll
    for (int i = 0; i < 2; i++) {
        int r0 = m0 + wm + i * 16 + qr;
#pragma unroll
        for (int j = 0; j < 8; j++) {
            int cc = n0 + wn + j * 8 + qc * 2;
            float* cp = Cp + (size_t)r0 * NPIX + cc;
            *(float2*)cp = make_float2(acc[i][j][0], acc[i][j][1]);
            *(float2*)(cp + (size_t)8 * NPIX) = make_float2(acc[i][j][2], acc[i][j][3]);
        }
    }
}

// ================= fp32 -> bf16 hi/lo converters =================
__global__ void cvt_split(const float* __restrict__ in, __nv_bfloat16* __restrict__ hi,
                          __nv_bfloat16* __restrict__ lo, int n) {
    int i = blockIdx.x * 256 + threadIdx.x;
    if (i >= n) return;
    float v = in[i];
    __nv_bfloat16 h = __float2bfloat16_rn(v);
    hi[i] = h;
    lo[i] = __float2bfloat16_rn(v - __bfloat162float(h));
}

__global__ void transpose_split(const float* __restrict__ x, __nv_bfloat16* __restrict__ th,
                                __nv_bfloat16* __restrict__ tl) {
    __shared__ float t[32][33];
    int b = blockIdx.z;
    int n0 = blockIdx.x * 32, c0 = blockIdx.y * 32;
    t[threadIdx.y][threadIdx.x] =
        x[((size_t)b * CDIM + c0 + threadIdx.y) * NPIX + n0 + threadIdx.x];
    __syncthreads();
    float v = t[threadIdx.x][threadIdx.y];
    __nv_bfloat16 h = __float2bfloat16_rn(v);
    size_t o = ((size_t)b * NPIX + n0 + threadIdx.y) * CDIM + c0 + threadIdx.x;
    th[o] = h;
    tl[o] = __float2bfloat16_rn(v - __bfloat162float(h));
}

// ================= vectorized depthwise 3x3, SAME =================
template <int MODE>
__global__ void dwconv3x3v(const float* __restrict__ in, const float* __restrict__ w,
                           float* __restrict__ out, int CH,
                           size_t inStride, size_t outStride, int totalq) {
    int idx = blockIdx.x * 256 + threadIdx.x;
    if (idx >= totalq) return;
    int x4 = (idx & 31) * 4;
    int y = (idx >> 5) & 127;
    int ch = (idx >> 12) % CH;
    int b = idx / (CH << 12);
    const float* ip = in + (size_t)b * inStride + (size_t)ch * NPIX;
    const float* wp = w + ch * 9;
    float w00 = wp[0], w01 = wp[1], w02 = wp[2];
    float w10 = wp[3], w11 = wp[4], w12 = wp[5];
    float w20 = wp[6], w21 = wp[7], w22 = wp[8];

    float o0 = 0.f, o1 = 0.f, o2 = 0.f, o3 = 0.f;
#pragma unroll
    for (int ky = 0; ky < 3; ky++) {
        int yy = y + ky - 1;
        if (yy < 0 || yy > 127) continue;
        const float* rp = ip + yy * 128;
        float4 c = *(const float4*)(rp + x4);
        float lft = (x4 > 0) ? rp[x4 - 1] : 0.f;
        float rgt = (x4 < 124) ? rp[x4 + 4] : 0.f;
        float wa = (ky == 0) ? w00 : (ky == 1) ? w10 : w20;
        float wb = (ky == 0) ? w01 : (ky == 1) ? w11 : w21;
        float wc = (ky == 0) ? w02 : (ky == 1) ? w12 : w22;
        o0 += wa * lft + wb * c.x + wc * c.y;
        o1 += wa * c.x + wb * c.y + wc * c.z;
        o2 += wa * c.y + wb * c.z + wc * c.w;
        o3 += wa * c.z + wb * c.w + wc * rgt;
    }
    float* op = out + (size_t)b * outStride + (size_t)ch * NPIX + y * 128 + x4;
    if (MODE == 0) {
        *(float4*)op = make_float4(o0, o1, o2, o3);
    } else if (MODE == 1) {
        float4 r;
        r.x = 0.5f * o0 * (1.0f + erff(o0 * 0.70710678118654752f));
        r.y = 0.5f * o1 * (1.0f + erff(o1 * 0.70710678118654752f));
        r.z = 0.5f * o2 * (1.0f + erff(o2 * 0.70710678118654752f));
        r.w = 0.5f * o3 * (1.0f + erff(o3 * 0.70710678118654752f));
        *(float4*)op = r;
    } else {
        float4 prev = *(const float4*)op;
        *(float4*)op = make_float4(prev.x + o0, prev.y + o1, prev.z + o2, prev.w + o3);
    }
}

// ================= per-row inverse L2 norms (float4) =================
__global__ void rownorm_kernel(const float* __restrict__ qk, float* __restrict__ invn) {
    int row = blockIdx.x;
    int b = row / 768, c = row % 768;
    const float* p = qk + ((size_t)b * C3 + c) * NPIX;
    float s = 0.f;
    for (int i = threadIdx.x; i < NPIX / 4; i += 256) {
        float4 v = *((const float4*)p + i);
        s += v.x * v.x + v.y * v.y + v.z * v.z + v.w * v.w;
    }
    __shared__ float red[8];
#pragma unroll
    for (int o = 16; o; o >>= 1) s += __shfl_down_sync(~0u, s, o);
    if ((threadIdx.x & 31) == 0) red[threadIdx.x >> 5] = s;
    __syncthreads();
    if (threadIdx.x < 8) {
        s = red[threadIdx.x];
#pragma unroll
        for (int o = 4; o; o >>= 1) s += __shfl_down_sync(0xffu, s, o);
        if (threadIdx.x == 0) invn[row] = 1.0f / fmaxf(sqrtf(s), 1e-12f);
    }
}

// ================= q.k^T partials =================
__global__ void attn_partial(const float* __restrict__ qkv, float* __restrict__ part) {
    __shared__ float qs[48][65];
    __shared__ float ks[48][65];
    const int split = blockIdx.x, h = blockIdx.y, b = blockIdx.z;
    const int tid = threadIdx.x;
    const float* qbase = qkv + ((size_t)b * C3 + h * CPH) * NPIX;
    const float* kbase = qkv + ((size_t)b * C3 + 384 + h * CPH) * NPIX;
    const int tx = tid & 15, ty = tid >> 4;
    const int c0 = ty * 3, d0 = tx * 3;
    float acc[3][3];
#pragma unroll
    for (int i = 0; i < 3; i++)
#pragma unroll
        for (int j = 0; j < 3; j++) acc[i][j] = 0.f;

    for (int chunk = 0; chunk < 16; chunk++) {
        int n0 = split * 1024 + chunk * 64;
        __syncthreads();
#pragma unroll
        for (int r = 0; r < 3; r++) {
            int v = tid + r * 256;
            int row = v >> 4;
            int col = (v & 15) << 2;
            float4 q4 = *(const float4*)(qbase + (size_t)row * NPIX + n0 + col);
            qs[row][col] = q4.x; qs[row][col + 1] = q4.y;
            qs[row][col + 2] = q4.z; qs[row][col + 3] = q4.w;
            float4 k4 = *(const float4*)(kbase + (size_t)row * NPIX + n0 + col);
            ks[row][col] = k4.x; ks[row][col + 1] = k4.y;
            ks[row][col + 2] = k4.z; ks[row][col + 3] = k4.w;
        }
        __syncthreads();
#pragma unroll 16
        for (int i = 0; i < 64; i++) {
            float q0 = qs[c0][i], q1 = qs[c0 + 1][i], q2 = qs[c0 + 2][i];
            float k0v = ks[d0][i], k1v = ks[d0 + 1][i], k2v = ks[d0 + 2][i];
            acc[0][0] += q0 * k0v; acc[0][1] += q0 * k1v; acc[0][2] += q0 * k2v;
            acc[1][0] += q1 * k0v; acc[1][1] += q1 * k1v; acc[1][2] += q1 * k2v;
            acc[2][0] += q2 * k0v; acc[2][1] += q2 * k1v; acc[2][2] += q2 * k2v;
        }
    }
    float* pp = part + ((size_t)((b * NHEADS + h) * 16 + split)) * 2304;
#pragma unroll
    for (int i = 0; i < 3; i++)
#pragma unroll
        for (int j = 0; j < 3; j++) pp[(c0 + i) * 48 + d0 + j] = acc[i][j];
}

__global__ void attn_reduce(const float* __restrict__ part, const float* __restrict__ invn,
                            const float* __restrict__ temp, float* __restrict__ logits) {
    int idx = blockIdx.x * 256 + threadIdx.x;
    if (idx >= 32 * 2304) return;
    int bh = idx / 2304, o = idx % 2304;
    int b = bh / NHEADS, h = bh % NHEADS;
    int c = o / 48, d = o % 48;
    float s = 0.f;
#pragma unroll
    for (int sp = 0; sp < 16; sp++) s += part[((size_t)bh * 16 + sp) * 2304 + o];
    float inq = invn[b * 768 + h * CPH + c];
    float ink = invn[b * 768 + 384 + h * CPH + d];
    logits[idx] = s * inq * ink * temp[h];
}

__global__ void softmax_blend(const float* __restrict__ logits, const int* __restrict__ mask,
                              const float* __restrict__ wb, float* __restrict__ probs) {
    int row = blockIdx.x;
    int c = row % 48;
    int h = (row / 48) % NHEADS;
    int lane = threadIdx.x;
    int d1 = lane + 32;
    const float* lp = logits + (size_t)row * 48;
    const int* mp = mask + (h * 48 + c) * 48;
    bool v1ok = d1 < 48;
    float a0 = lp[lane];
    float a1 = v1ok ? lp[d1] : -INFINITY;
    float b0 = (mp[lane] == 0) ? -1e9f : a0;
    float b1 = v1ok ? ((mp[d1] == 0) ? -1e9f : a1) : -INFINITY;
    float mA = fmaxf(a0, a1), mB = fmaxf(b0, b1);
#pragma unroll
    for (int o = 16; o; o >>= 1) {
        mA = fmaxf(mA, __shfl_xor_sync(~0u, mA, o));
        mB = fmaxf(mB, __shfl_xor_sync(~0u, mB, o));
    }
    float eA0 = expf(a0 - mA);
    float eA1 = v1ok ? expf(a1 - mA) : 0.f;
    float eB0 = expf(b0 - mB);
    float eB1 = v1ok ? expf(b1 - mB) : 0.f;
    float sA = eA0 + eA1, sB = eB0 + eB1;
#pragma unroll
    for (int o = 16; o; o >>= 1) {
        sA += __shfl_xor_sync(~0u, sA, o);
        sB += __shfl_xor_sync(~0u, sB, o);
    }
    float w0 = wb[0], w1 = wb[1];
    float wm = fmaxf(w0, w1);
    float ew0 = expf(w0 - wm), ew1 = expf(w1 - wm);
    float wsum = ew0 + ew1;
    float blend0 = ew0 / wsum, blend1 = ew1 / wsum;
    float* pp = probs + (size_t)row * 48;
    pp[lane] = blend0 * eA0 / sA + blend1 * eB0 / sB;
    if (v1ok) pp[d1] = blend0 * eA1 / sA + blend1 * eB1 / sB;
}

// ================= out = attn @ v -> transposed bf16 hi/lo (SMEM-staged coalesced stores) =================
__global__ void attnv(const float* __restrict__ probs, const float* __restrict__ qkv2,
                      __nv_bfloat16* __restrict__ th, __nv_bfloat16* __restrict__ tl) {
    __shared__ float a_s[2304];
    __shared__ uint32_t sh[2][128][26];  // 24 used + 2 pad (bank spread, 8B-aligned rows)
    const int h = blockIdx.y, b = blockIdx.z;
    const int tid = threadIdx.x;
    const int n0 = blockIdx.x * 128;
    const int n = n0 + tid;
    const float* ap = probs + (size_t)(b * NHEADS + h) * 2304;
    for (int i = tid; i < 2304; i += 128) a_s[i] = ap[i];
    __syncthreads();
    const float* vbase = qkv2 + ((size_t)b * C3 + 768 + h * CPH) * NPIX + n;
    float vr[48];
#pragma unroll
    for (int d = 0; d < 48; d++) vr[d] = vbase[(size_t)d * NPIX];
    float accv[48];
#pragma unroll 4
    for (int c = 0; c < 48; c++) {
        float acc = 0.f;
#pragma unroll
        for (int d = 0; d < 48; d++) acc += a_s[c * 48 + d] * vr[d];
        accv[c] = acc;
    }
    // pack to bf16 hi/lo pairs in smem
#pragma unroll
    for (int c2 = 0; c2 < 24; c2++) {
        float v0 = accv[2 * c2], v1 = accv[2 * c2 + 1];
        __nv_bfloat16 h0 = __float2bfloat16_rn(v0);
        __nv_bfloat16 h1 = __float2bfloat16_rn(v1);
        __nv_bfloat16 l0 = __float2bfloat16_rn(v0 - __bfloat162float(h0));
        __nv_bfloat16 l1 = __float2bfloat16_rn(v1 - __bfloat162float(h1));
        sh[0][tid][c2] = (uint32_t)__bfloat16_as_ushort(h0) |
                         ((uint32_t)__bfloat16_as_ushort(h1) << 16);
        sh[1][tid][c2] = (uint32_t)__bfloat16_as_ushort(l0) |
                         ((uint32_t)__bfloat16_as_ushort(l1) << 16);
    }
    __syncthreads();
    // coalesced writes: per row 48 bf16 = 96B = 12 uint2
    for (int idx = tid; idx < 2 * 128 * 12; idx += 128) {
        int a = idx / (128 * 12);
        int r = (idx / 12) & 127;
        int j = idx % 12;
        uint2 v = *(const uint2*)&sh[a][r][j * 2];
        __nv_bfloat16* base = a ? tl : th;
        *((uint2*)(base + ((size_t)b * NPIX + n0 + r) * CDIM + h * CPH) + j) = v;
    }
}

// ================= launch =================
extern "C" void kernel_launch(void* const* d_in, const int* in_sizes, int n_in,
                              void* d_out, int out_size) {
    const float* x           = (const float*)d_in[0];
    const int*   mask        = (const int*)d_in[1];
    const float* qkv_w       = (const float*)d_in[2];
    const float* dw_w        = (const float*)d_in[3];
    const float* proj_w      = (const float*)d_in[4];
    const float* temperature = (const float*)d_in[5];
    const float* w_blend     = (const float*)d_in[6];
    const float* pos_w1      = (const float*)d_in[7];
    const float* pos_w2      = (const float*)d_in[8];
    float* out = (float*)d_out;

    float *qkv1, *qkv2, *norm, *part, *logits, *probs, *pos1;
    __nv_bfloat16 *xh, *xl, *ah, *al, *wqh, *wql, *wph, *wpl;
    cudaGetSymbolAddress((void**)&qkv1, g_qkv1);
    cudaGetSymbolAddress((void**)&qkv2, g_qkv2);
    cudaGetSymbolAddress((void**)&norm, g_norm);
    cudaGetSymbolAddress((void**)&part, g_part);
    cudaGetSymbolAddress((void**)&logits, g_logits);
    cudaGetSymbolAddress((void**)&probs, g_probs);
    cudaGetSymbolAddress((void**)&pos1, g_pos1);
    cudaGetSymbolAddress((void**)&xh, g_xT_hi);
    cudaGetSymbolAddress((void**)&xl, g_xT_lo);
    cudaGetSymbolAddress((void**)&ah, g_aT_hi);
    cudaGetSymbolAddress((void**)&al, g_aT_lo);
    cudaGetSymbolAddress((void**)&wqh, g_wq_hi);
    cudaGetSymbolAddress((void**)&wql, g_wq_lo);
    cudaGetSymbolAddress((void**)&wph, g_wp_hi);
    cudaGetSymbolAddress((void**)&wpl, g_wp_lo);

    static bool attr_set = false;
    if (!attr_set) {
        cudaFuncSetAttribute(gemm_hmma, cudaFuncAttributeMaxDynamicSharedMemorySize, GEMM_SMEM);
        attr_set = true;
    }

    // 0) operand conversion
    cvt_split<<<(C3 * CDIM + 255) / 256, 256>>>(qkv_w, wqh, wql, C3 * CDIM);
    cvt_split<<<(CDIM * CDIM + 255) / 256, 256>>>(proj_w, wph, wpl, CDIM * CDIM);
    transpose_split<<<dim3(NPIX / 32, CDIM / 32, BATCH), dim3(32, 32)>>>(x, xh, xl);

    // 1) qkv 1x1 conv via HMMA
    gemm_hmma<<<dim3(C3 / 128, NPIX / 128, BATCH), 256, GEMM_SMEM>>>(
        wqh, wql, xh, xl, qkv1, (size_t)NPIX * CDIM, (size_t)C3 * NPIX);

    // 2) depthwise 3x3 (vectorized)
    {
        int totalq = BATCH * C3 * NPIX / 4;
        dwconv3x3v<0><<<(totalq + 255) / 256, 256>>>(
            qkv1, dw_w, qkv2, C3, (size_t)C3 * NPIX, (size_t)C3 * NPIX, totalq);
    }

    // 3) q,k row norms
    rownorm_kernel<<<BATCH * 768, 256>>>(qkv2, norm);

    // 4) q.k^T + reduce
    attn_partial<<<dim3(16, NHEADS, BATCH), 256>>>(qkv2, part);
    attn_reduce<<<(32 * 2304 + 255) / 256, 256>>>(part, norm, temperature, logits);

    // 5) dual softmax blend
    softmax_blend<<<BATCH * NHEADS * 48, 32>>>(logits, mask, w_blend, probs);

    // 6) attn @ v -> transposed bf16 hi/lo (coalesced)
    attnv<<<dim3(NPIX / 128, NHEADS, BATCH), 128>>>(probs, qkv2, ah, al);

    // 7) proj 1x1 conv via HMMA
    gemm_hmma<<<dim3(CDIM / 128, NPIX / 128, BATCH), 256, GEMM_SMEM>>>(
        wph, wpl, ah, al, out, (size_t)NPIX * CDIM, (size_t)CDIM * NPIX);

    // 8) pos path added into d_out (vectorized)
    {
        int totalq = BATCH * CDIM * NPIX / 4;
        dwconv3x3v<1><<<(totalq + 255) / 256, 256>>>(
            qkv2 + (size_t)768 * NPIX, pos_w1, pos1, CDIM,
            (size_t)C3 * NPIX, (size_t)CDIM * NPIX, totalq);
        dwconv3x3v<2><<<(totalq + 255) / 256, 256>>>(
            pos1, pos_w2, out, CDIM,
            (size_t)CDIM * NPIX, (size_t)CDIM * NPIX, totalq);
    }
}